// round 6
// baseline (speedup 1.0000x reference)
#include <cuda_runtime.h>
#include <cuda_fp16.h>

#define NUM_BUCKETS 9311
#define L 8          // categories per (b,c)
#define ROW_U2 16    // 64 halves per table row = 16 uint2 (8 B per lane)

// fp16 copy of the embedding table: 9311 rows x 64 ch = 1.19 MB scratch.
__device__ __half2 g_tab16[NUM_BUCKETS * 32];

__global__ void __launch_bounds__(256)
convert_kernel(const float2* __restrict__ table_f32) {
    int i = blockIdx.x * blockDim.x + threadIdx.x;       // one half2 per thread
    if (i < NUM_BUCKETS * 32) {
        float2 v = table_f32[i];
        g_tab16[i] = __floats2half2_rn(v.x, v.y);
    }
}

// Table gather: LDG.64 with L1 evict_last (bias L1 toward keeping table rows).
__device__ __forceinline__ uint2 ldg_tab(const uint2* p) {
    uint2 r;
    asm volatile("ld.global.nc.L1::evict_last.v2.u32 {%0,%1}, [%2];"
                 : "=r"(r.x), "=r"(r.y) : "l"(p));
    return r;
}

__global__ void __launch_bounds__(256)
enc_kernel(const int2* __restrict__ x2,
           float4* __restrict__ out,
           int n_pairs) {           // n_rows/2; each warp iteration does 2 rows
    int wid0 = (blockIdx.x * blockDim.x + threadIdx.x) >> 5;
    int total_warps = (gridDim.x * blockDim.x) >> 5;
    int lane = threadIdx.x & 31;
    int half = lane >> 4;      // which of the 2 rows this warp handles per iter
    int sub  = lane & 15;      // uint2 slot within the 64-channel fp16 row
    int base = half << 4;

    const uint2* tab = reinterpret_cast<const uint2*>(g_tab16) + sub;

    int p = wid0;
    if (p >= n_pairs) return;

    // Prologue: load indices for first pair. Lanes sub<4 each load 2 indices
    // (streaming: x is read exactly once).
    int2 xcur = make_int2(0, 0);
    if (sub < 4) xcur = __ldcs(&x2[(p * 2 + half) * 4 + sub]);

    for (; p < n_pairs; p += total_warps) {
        int pn = p + total_warps;
        int row = p * 2 + half;

        // Pack two (hash<<1|mask) 15-bit codes per int (lanes sub<4).
        int packed = 0;
        if (sub < 4) {
            int a = max(xcur.x, 0);
            int b = max(xcur.y, 0);
            int ha = a % NUM_BUCKETS;
            int hb = b % NUM_BUCKETS;
            packed = ((ha << 1) | (a > 0 ? 1 : 0)) | ((((hb << 1) | (b > 0 ? 1 : 0))) << 16);
        }

        int p0 = __shfl_sync(0xffffffffu, packed, base + 0);
        int p1 = __shfl_sync(0xffffffffu, packed, base + 1);
        int p2 = __shfl_sync(0xffffffffu, packed, base + 2);
        int p3 = __shfl_sync(0xffffffffu, packed, base + 3);

        // Prefetch next pair's indices: independent of gathers, overlaps their latency.
        int2 xnext = make_int2(0, 0);
        if (sub < 4) {
            int psrc = (pn < n_pairs) ? pn : p;
            xnext = __ldcs(&x2[(psrc * 2 + half) * 4 + sub]);
        }

        int h0 = (p0 >> 1) & 0x7FFF, h1 = p0 >> 17;
        int h2 = (p1 >> 1) & 0x7FFF, h3 = p1 >> 17;
        int h4 = (p2 >> 1) & 0x7FFF, h5 = p2 >> 17;
        int h6 = (p3 >> 1) & 0x7FFF, h7 = p3 >> 17;

        const int M = 0x00010001;
        int cnt = __popc((p0 & M) | ((p1 & M) << 2) | ((p2 & M) << 4) | ((p3 & M) << 6));

        // 8 unconditional fp16 gathers (table row 0 is zeros -> masked entries add 0).
        uint2 g0 = ldg_tab(tab + h0 * ROW_U2);
        uint2 g1 = ldg_tab(tab + h1 * ROW_U2);
        uint2 g2 = ldg_tab(tab + h2 * ROW_U2);
        uint2 g3 = ldg_tab(tab + h3 * ROW_U2);
        uint2 g4 = ldg_tab(tab + h4 * ROW_U2);
        uint2 g5 = ldg_tab(tab + h5 * ROW_U2);
        uint2 g6 = ldg_tab(tab + h6 * ROW_U2);
        uint2 g7 = ldg_tab(tab + h7 * ROW_U2);

        // Full HADD2 tree (14 ops), widen once, scale in f32.
        #define H2(v) (*reinterpret_cast<const __half2*>(&(v)))
        __half2 a01 = __hadd2(H2(g0.x), H2(g1.x));
        __half2 b01 = __hadd2(H2(g0.y), H2(g1.y));
        __half2 a23 = __hadd2(H2(g2.x), H2(g3.x));
        __half2 b23 = __hadd2(H2(g2.y), H2(g3.y));
        __half2 a45 = __hadd2(H2(g4.x), H2(g5.x));
        __half2 b45 = __hadd2(H2(g4.y), H2(g5.y));
        __half2 a67 = __hadd2(H2(g6.x), H2(g7.x));
        __half2 b67 = __hadd2(H2(g6.y), H2(g7.y));
        __half2 a03 = __hadd2(a01, a23);
        __half2 b03 = __hadd2(b01, b23);
        __half2 a47 = __hadd2(a45, a67);
        __half2 b47 = __hadd2(b45, b67);
        __half2 sa  = __hadd2(a03, a47);
        __half2 sb  = __hadd2(b03, b47);
        #undef H2

        float2 fa = __half22float2(sa);
        float2 fb = __half22float2(sb);

        float inv = __fdividef(1.0f, (float)(cnt > 0 ? cnt : 1));
        float4 res = make_float4(fa.x * inv, fa.y * inv, fb.x * inv, fb.y * inv);

        out[(long long)row * 16 + sub] = res;

        xcur = xnext;
    }
}

extern "C" void kernel_launch(void* const* d_in, const int* in_sizes, int n_in,
                              void* d_out, int out_size) {
    const int2*   x2   = (const int2*)d_in[0];
    const float2* tabf = (const float2*)d_in[1];
    float4*       out  = (float4*)d_out;

    // 1) table f32 -> fp16 scratch (idempotent, graph-capturable)
    int n_h2 = NUM_BUCKETS * 32;
    convert_kernel<<<(n_h2 + 255) / 256, 256>>>(tabf);

    // 2) persistent gather kernel: exactly one full wave on 148 SMs
    //    (1184 blocks x 256 thr = 303104 threads = 148 SMs x 2048).
    int n_rows  = in_sizes[0] / L;       // B*C = 262144
    int n_pairs = n_rows / 2;            // 131072 (n_rows is even)
    int threads = 256;
    int blocks  = 1184;

    enc_kernel<<<blocks, threads>>>(x2, out, n_pairs);
}

// round 7
// speedup vs baseline: 1.0531x; 1.0531x over previous
#include <cuda_runtime.h>
#include <cuda_fp16.h>

#define NUM_BUCKETS 9311
#define L 8          // categories per (b,c)

// fp16 copy of the embedding table: 9311 rows x 64 ch = 1.19 MB scratch.
__device__ __half2 g_tab16[NUM_BUCKETS * 32];

__global__ void __launch_bounds__(256)
convert_kernel(const float2* __restrict__ table_f32) {
    int i = blockIdx.x * blockDim.x + threadIdx.x;       // one half2 per thread
    if (i < NUM_BUCKETS * 32) {
        float2 v = table_f32[i];
        g_tab16[i] = __floats2half2_rn(v.x, v.y);
    }
}

// Table gather: LDG.128 with L1 evict_last (bias L1 toward keeping table rows).
__device__ __forceinline__ uint4 ldg_tab(const uint4* p) {
    uint4 r;
    asm volatile("ld.global.nc.L1::evict_last.v4.u32 {%0,%1,%2,%3}, [%4];"
                 : "=r"(r.x), "=r"(r.y), "=r"(r.z), "=r"(r.w) : "l"(p));
    return r;
}

__global__ void __launch_bounds__(256)
enc_kernel(const int* __restrict__ x,
           float4* __restrict__ out,
           int n_rows) {
    int warp = (blockIdx.x * blockDim.x + threadIdx.x) >> 5;
    int lane = threadIdx.x & 31;
    int group = lane >> 3;     // 4 rows per warp, 8 lanes per row
    int gl    = lane & 7;      // 16-byte slot within the 128-B fp16 table row

    int row = warp * 4 + group;
    bool valid = (row < n_rows);

    // One index per lane: lane l covers (row_group, slot) = (l>>3, l&7).
    // 128 B coalesced per warp; x is read exactly once -> streaming.
    long long xi = (long long)warp * 32 + lane;
    int v = valid ? __ldcs(&x[xi]) : 0;

    int a = max(v, 0);
    int h = a % NUM_BUCKETS;                 // scalar hash per lane

    // Valid count per row via one ballot.
    unsigned bal = __ballot_sync(0xffffffffu, v > 0);
    int cnt = __popc((bal >> (group * 8)) & 0xFF);

    // Broadcast the 8 hashes of this lane's row-group; gathers are
    // unconditional (table row 0 is all zeros -> masked entries add 0).
    const uint4* tab = reinterpret_cast<const uint4*>(g_tab16) + gl;  // row stride = 8 uint4
    int hb = group << 3;
    int h0 = __shfl_sync(0xffffffffu, h, hb + 0);
    int h1 = __shfl_sync(0xffffffffu, h, hb + 1);
    int h2 = __shfl_sync(0xffffffffu, h, hb + 2);
    int h3 = __shfl_sync(0xffffffffu, h, hb + 3);
    int h4 = __shfl_sync(0xffffffffu, h, hb + 4);
    int h5 = __shfl_sync(0xffffffffu, h, hb + 5);
    int h6 = __shfl_sync(0xffffffffu, h, hb + 6);
    int h7 = __shfl_sync(0xffffffffu, h, hb + 7);

    // 8 independent LDG.128, front-batched (each instruction fetches 4 table rows).
    uint4 g0 = ldg_tab(tab + h0 * 8);
    uint4 g1 = ldg_tab(tab + h1 * 8);
    uint4 g2 = ldg_tab(tab + h2 * 8);
    uint4 g3 = ldg_tab(tab + h3 * 8);
    uint4 g4 = ldg_tab(tab + h4 * 8);
    uint4 g5 = ldg_tab(tab + h5 * 8);
    uint4 g6 = ldg_tab(tab + h6 * 8);
    uint4 g7 = ldg_tab(tab + h7 * 8);

    // HADD2 tree over 8 gathers x 4 half2 components (28 HADD2).
    #define H2(w) (*reinterpret_cast<const __half2*>(&(w)))
    __half2 s0x = __hadd2(H2(g0.x), H2(g1.x)), s1x = __hadd2(H2(g2.x), H2(g3.x));
    __half2 s2x = __hadd2(H2(g4.x), H2(g5.x)), s3x = __hadd2(H2(g6.x), H2(g7.x));
    __half2 s0y = __hadd2(H2(g0.y), H2(g1.y)), s1y = __hadd2(H2(g2.y), H2(g3.y));
    __half2 s2y = __hadd2(H2(g4.y), H2(g5.y)), s3y = __hadd2(H2(g6.y), H2(g7.y));
    __half2 s0z = __hadd2(H2(g0.z), H2(g1.z)), s1z = __hadd2(H2(g2.z), H2(g3.z));
    __half2 s2z = __hadd2(H2(g4.z), H2(g5.z)), s3z = __hadd2(H2(g6.z), H2(g7.z));
    __half2 s0w = __hadd2(H2(g0.w), H2(g1.w)), s1w = __hadd2(H2(g2.w), H2(g3.w));
    __half2 s2w = __hadd2(H2(g4.w), H2(g5.w)), s3w = __hadd2(H2(g6.w), H2(g7.w));
    __half2 tx = __hadd2(__hadd2(s0x, s1x), __hadd2(s2x, s3x));
    __half2 ty = __hadd2(__hadd2(s0y, s1y), __hadd2(s2y, s3y));
    __half2 tz = __hadd2(__hadd2(s0z, s1z), __hadd2(s2z, s3z));
    __half2 tw = __hadd2(__hadd2(s0w, s1w), __hadd2(s2w, s3w));
    #undef H2

    float2 fx = __half22float2(tx);
    float2 fy = __half22float2(ty);
    float2 fz = __half22float2(tz);
    float2 fw = __half22float2(tw);

    float inv = __fdividef(1.0f, (float)(cnt > 0 ? cnt : 1));
    float4 r0 = make_float4(fx.x * inv, fx.y * inv, fy.x * inv, fy.y * inv);
    float4 r1 = make_float4(fz.x * inv, fz.y * inv, fw.x * inv, fw.y * inv);

    // Lane gl holds channels [8*gl, 8*gl+8) -> float4 slots 2*gl and 2*gl+1.
    if (valid) {
        float4* orow = out + (long long)row * 16 + gl * 2;
        orow[0] = r0;
        orow[1] = r1;
    }
}

extern "C" void kernel_launch(void* const* d_in, const int* in_sizes, int n_in,
                              void* d_out, int out_size) {
    const int*    xptr = (const int*)d_in[0];
    const float2* tabf = (const float2*)d_in[1];
    float4*       out  = (float4*)d_out;

    // 1) table f32 -> fp16 scratch (idempotent, graph-capturable)
    int n_h2 = NUM_BUCKETS * 32;
    convert_kernel<<<(n_h2 + 255) / 256, 256>>>(tabf);

    // 2) main gather kernel: 8 warps/block, 4 rows/warp -> 32 rows/block
    int n_rows = in_sizes[0] / L;        // B*C = 262144
    int threads = 256;
    int rows_per_block = (threads / 32) * 4;
    int blocks = (n_rows + rows_per_block - 1) / rows_per_block;   // 8192

    enc_kernel<<<blocks, threads>>>(xptr, out, n_rows);
}